// round 16
// baseline (speedup 1.0000x reference)
#include <cuda_runtime.h>
#include <cstdint>

// ============================================================================
// AdditiveAttention fused kernels for GB300 (sm_103a) — Round 16
//   proj: TF32 mma.m16n8k8, STATIC chunk=block mapping (grid=320),
//         3-stage cp.async pipeline (wait_group 1)
//   attn: R15 config frozen (QT=16, 256 thr, split-K S=8, smem-broadcast AV)
// ============================================================================

#define NEG_FILL (-1e6f)
#define S_SPLIT 8
#define QT 16
#define KT 32
#define KP 132

#define NQCHUNK 64             // 2048 q rows / 32
#define NCHUNK  320            // 64 q chunks + 256 k chunks (8192 rows / 32)

// Scratch (allocation-free: __device__ globals; zero-init at module load)
__device__ float g_qh[8 * 256 * 128];                 // 1 MB
__device__ float g_kh[8 * 1024 * 128];                // 4 MB
__device__ float g_po[S_SPLIT * 2048 * 128];          // 8 MB partial o
__device__ float g_pl[S_SPLIT * 2048];                // 64 KB partial l

__device__ __forceinline__ float fast_tanh(float x) {
    float y;
    asm("tanh.approx.f32 %0, %1;" : "=f"(y) : "f"(x));
    return y;
}
__device__ __forceinline__ void cp16(uint32_t s, const void* g) {
    asm volatile("cp.async.cg.shared.global [%0], [%1], 16;" :: "r"(s), "l"(g));
}
#define CP_COMMIT() asm volatile("cp.async.commit_group;")
#define CP_WAIT0()  asm volatile("cp.async.wait_group 0;")
#define CP_WAIT1()  asm volatile("cp.async.wait_group 1;")

__device__ __forceinline__ uint32_t f2tf32(float x) {
    uint32_t r;
    asm("cvt.rna.tf32.f32 %0, %1;" : "=r"(r) : "f"(x));
    return r;
}
__device__ __forceinline__ void mma_tf32(
    float& d0, float& d1, float& d2, float& d3,
    uint32_t a0, uint32_t a1, uint32_t a2, uint32_t a3,
    uint32_t b0, uint32_t b1)
{
    asm("mma.sync.aligned.m16n8k8.row.col.f32.tf32.tf32.f32 "
        "{%0,%1,%2,%3},{%4,%5,%6,%7},{%8,%9},{%0,%1,%2,%3};"
        : "+f"(d0), "+f"(d1), "+f"(d2), "+f"(d3)
        : "r"(a0), "r"(a1), "r"(a2), "r"(a3), "r"(b0), "r"(b1));
}

// ----------------------------------------------------------------------------
// Projection GEMM, TF32 tensor cores, static chunk=blockIdx.x, 3-stage pipe.
// Chunk = 32 output rows x 128 cols, K=256. chunks 0..63 -> q, 64..319 -> k
// (32 per batch; masked chunks exit immediately).
// Block = 256 threads (8 warps). Warp w: rows (w>>2)*16..+15,
// cols (w&3)*32..+31 (4 mma n-tiles of 8). K-tile = 32 (4 mma k8-steps).
// smem (floats): Xs[3][32][36] @ 0 (3456)      A-frag banks 4*gid+t4: CF
//                Ws[3][32][136] @ 3456 (13056) B-frag banks 8*t4+gid: CF
//                total 16512 floats = 66048 B
// ----------------------------------------------------------------------------
__global__ __launch_bounds__(256) void proj_kernel(
    const float* __restrict__ Xq, const float* __restrict__ Xk,
    const float* __restrict__ Wq, const float* __restrict__ Wk,
    const int* __restrict__ valid_lens)
{
    __shared__ float sm[16512];

    int tid  = threadIdx.x;
    int w    = tid >> 5;
    int lane = tid & 31;
    int gid  = lane >> 2;           // 0..7
    int t4   = lane & 3;            // 0..3
    int rowbase = (w >> 2) << 4;    // 0 or 16
    int ncol0   = (w & 3) << 5;     // 0,32,64,96

    int c = blockIdx.x;             // static chunk id
    const float* X; const float* W; float* Y; int row0;
    if (c < NQCHUNK) {
        X = Xq; W = Wq; Y = g_qh; row0 = c << 5;
    } else {
        int kc = c - NQCHUNK;           // 0..255, 32 per batch
        int b  = kc >> 5;
        if (((kc & 31) << 5) >= valid_lens[b]) return;  // never read downstream
        X = Xk; W = Wk; Y = g_kh; row0 = kc << 5;
    }

    uint32_t su = (uint32_t)__cvta_generic_to_shared(sm);

    // cp.async mapping
    // X k-tile: 32 rows x 32 floats = 256 x 16B chunks, 1/thread
    int xrow  = tid >> 3;           // 0..31
    int xcol4 = (tid & 7) << 2;     // 0..28
    uint32_t xdst = su + (uint32_t)(xrow * 36 + xcol4) * 4u;
    // W k-tile: 32 rows x 128 floats = 1024 x 16B chunks, 4/thread
    int wrow[4], wcol4[4];
    uint32_t wdst[4];
#pragma unroll
    for (int j = 0; j < 4; j++) {
        int id = tid + (j << 8);
        wrow[j]  = id >> 5;         // 0..31
        wcol4[j] = (id & 31) << 2;  // 0..124
        wdst[j]  = su + (uint32_t)(3456 + wrow[j] * 136 + wcol4[j]) * 4u;
    }
    const uint32_t XB = 1152u * 4u;   // bytes per X buffer
    const uint32_t WB = 4352u * 4u;   // bytes per W buffer

    const float* Xg = &X[(row0 + xrow) * 256 + xcol4];  // + k0

    // prologue: k-tiles 0 and 1 into bufs 0 and 1 (two commit groups)
    cp16(xdst, Xg);
#pragma unroll
    for (int j = 0; j < 4; j++)
        cp16(wdst[j], &W[wrow[j] * 128 + wcol4[j]]);
    CP_COMMIT();
    cp16(xdst + XB, Xg + 32);
#pragma unroll
    for (int j = 0; j < 4; j++)
        cp16(wdst[j] + WB, &W[(32 + wrow[j]) * 128 + wcol4[j]]);
    CP_COMMIT();

    float d[4][4];
#pragma unroll
    for (int j = 0; j < 4; j++)
#pragma unroll
        for (int i = 0; i < 4; i++) d[j][i] = 0.f;

    int buf = 0;                // buffer holding tile `it`
    for (int it = 0; it < 8; it++) {
        CP_WAIT1();             // all groups but newest done -> tile it ready
        __syncthreads();        // all warps finished reading buf being refilled

        if (it < 6) {           // issue tile it+2 into buffer (it+2)%3
            int nb = buf + 2; if (nb >= 3) nb -= 3;
            int k0 = (it + 2) << 5;
            uint32_t xo = (uint32_t)nb * XB;
            uint32_t wo = (uint32_t)nb * WB;
            cp16(xdst + xo, Xg + k0);
#pragma unroll
            for (int j = 0; j < 4; j++)
                cp16(wdst[j] + wo, &W[(k0 + wrow[j]) * 128 + wcol4[j]]);
        }
        CP_COMMIT();            // unconditional: keeps group accounting exact

        const float* xb = sm + buf * 1152;
        const float* wb = sm + 3456 + buf * 4352;
        int ra = rowbase + gid;
#pragma unroll
        for (int kk = 0; kk < 32; kk += 8) {
            uint32_t a0 = f2tf32(xb[ra * 36 + kk + t4]);
            uint32_t a1 = f2tf32(xb[(ra + 8) * 36 + kk + t4]);
            uint32_t a2 = f2tf32(xb[ra * 36 + kk + t4 + 4]);
            uint32_t a3 = f2tf32(xb[(ra + 8) * 36 + kk + t4 + 4]);
#pragma unroll
            for (int j = 0; j < 4; j++) {
                int col = ncol0 + (j << 3) + gid;
                uint32_t b0 = f2tf32(wb[(kk + t4) * 136 + col]);
                uint32_t b1 = f2tf32(wb[(kk + t4 + 4) * 136 + col]);
                mma_tf32(d[j][0], d[j][1], d[j][2], d[j][3],
                         a0, a1, a2, a3, b0, b1);
            }
        }

        if (++buf == 3) buf = 0;
    }

    // epilogue: D fragments -> Y
    {
        int rhi = row0 + rowbase + gid;
#pragma unroll
        for (int j = 0; j < 4; j++) {
            int col = ncol0 + (j << 3) + (t4 << 1);
            float2 lo = {d[j][0], d[j][1]};
            float2 hi = {d[j][2], d[j][3]};
            *(float2*)&Y[rhi * 128 + col]       = lo;
            *(float2*)&Y[(rhi + 8) * 128 + col] = hi;
        }
    }
}

// ----------------------------------------------------------------------------
// Split-K score + exp + AV partial kernel, cp.async double-buffered.
// grid = (Q/QT=16, B, S_SPLIT), 256 threads, 8 warps, 2 q-rows per warp.
// AV uses a per-warp smem p-strip with float4 broadcast reads (no shfl).
// Dynamic smem layout (floats):
//   ks[2][32][132] @ 0        (8448)
//   vs[2][32][128] @ 8448     (8192)
//   qs[16][128]    @ 16640    (2048)
//   wv[128]        @ 18688    (128)
//   pb[8][2][32]   @ 18816    (512)    total 19328 floats = 77312 B
// ----------------------------------------------------------------------------
#define ATTN_SMEM_BYTES 77312

__global__ __launch_bounds__(256) void attn_partial_kernel(
    const float* __restrict__ V, const int* __restrict__ valid_lens,
    const float* __restrict__ w_v)
{
    extern __shared__ float sm[];
    float* qs = sm + 16640;
    float* wv = sm + 18688;
    float* pb = sm + 18816;

    int b    = blockIdx.y;
    int q0   = blockIdx.x * QT;
    int sp   = blockIdx.z;
    int tid  = threadIdx.x;
    int w    = tid >> 5;
    int lane = tid & 31;
    int nv   = valid_lens[b];          // 1..1024
    int ntiles = (nv + 31) >> 5;

    uint32_t su = (uint32_t)__cvta_generic_to_shared(sm);

    int lr = tid >> 3;                 // 0..31
    int lc = (tid & 7) << 2;           // float col base
    const float* gkb = g_kh + ((size_t)(b << 10) + lr) * 128 + lc;
    const float* gvb = V    + ((size_t)(b << 10) + lr) * 128 + lc;
    uint32_t ku0 = su + (uint32_t)(lr * KP  + lc) * 4u;
    uint32_t vu0 = su + (uint32_t)(8448 + lr * 128 + lc) * 4u;

    // prologue: issue tile sp into buf 0
    if (sp < ntiles) {
        const float* gk = gkb + (sp << 5) * 128;
        const float* gv = gvb + (sp << 5) * 128;
#pragma unroll
        for (int j = 0; j < 4; j++) {
            cp16(ku0 + j * 128u, gk + (j << 3) * 4);
            cp16(vu0 + j * 128u, gv + (j << 3) * 4);
        }
    }
    CP_COMMIT();

    // stage 16 q rows + w_v (overlaps with cp.async)
    {
        int r = tid >> 4;              // 0..15
        int c = (tid & 15) << 3;       // 0,8,...,120
        const float* src = &g_qh[((b << 8) + q0 + r) * 128 + c];
        *(float4*)&qs[r * 128 + c]     = *(const float4*)(src);
        *(float4*)&qs[r * 128 + c + 4] = *(const float4*)(src + 4);
    }
    if (tid < 128) wv[tid] = w_v[tid];

    float  l0 = 0.f, l1 = 0.f;
    float4 o0 = {0.f, 0.f, 0.f, 0.f};
    float4 o1 = {0.f, 0.f, 0.f, 0.f};

    const float* qsp0 = qs + (2 * w)     * 128;
    const float* qsp1 = qs + (2 * w + 1) * 128;
    float* pw = pb + w * 64;           // [2][32] strip for this warp

    int buf = 0;
    for (int t = sp; t < ntiles; t += S_SPLIT, buf ^= 1) {
        CP_WAIT0();
        __syncthreads();

        int tn = t + S_SPLIT;
        if (tn < ntiles) {
            uint32_t koff = (buf ^ 1) ? 0x4200u : 0u;   // 4224 floats * 4B
            uint32_t voff = (buf ^ 1) ? 0x4000u : 0u;   // 4096 floats * 4B
            const float* gk = gkb + (tn << 5) * 128;
            const float* gv = gvb + (tn << 5) * 128;
#pragma unroll
            for (int j = 0; j < 4; j++) {
                cp16(ku0 + koff + j * 128u, gk + (j << 3) * 4);
                cp16(vu0 + voff + j * 128u, gv + (j << 3) * 4);
            }
        }
        CP_COMMIT();

        // ---- scores for k = (t<<5) + lane, q rows 2w and 2w+1 ----
        const float* ksp = sm + buf * 4224 + lane * KP;
        float s0 = 0.f, s1 = 0.f;
#pragma unroll
        for (int h = 0; h < 128; h += 4) {
            float4 kv = *(float4*)&ksp[h];
            float4 w4 = *(float4*)&wv[h];
            float4 qa = *(float4*)&qsp0[h];
            float4 qb = *(float4*)&qsp1[h];
            s0 += fast_tanh(qa.x + kv.x) * w4.x;
            s1 += fast_tanh(qb.x + kv.x) * w4.x;
            s0 += fast_tanh(qa.y + kv.y) * w4.y;
            s1 += fast_tanh(qb.y + kv.y) * w4.y;
            s0 += fast_tanh(qa.z + kv.z) * w4.z;
            s1 += fast_tanh(qb.z + kv.z) * w4.z;
            s0 += fast_tanh(qa.w + kv.w) * w4.w;
            s1 += fast_tanh(qb.w + kv.w) * w4.w;
        }
        if ((t << 5) + lane >= nv) { s0 = NEG_FILL; s1 = NEG_FILL; }

        float p0 = __expf(s0);
        float p1 = __expf(s1);
        l0 += p0; l1 += p1;

        // publish p to the warp strip, then broadcast-read as float4
        pw[lane]      = p0;
        pw[32 + lane] = p1;
        __syncwarp();

        // ---- AV: one V read + one p4 pair per 4 k-steps ----
        const float* vsp = sm + 8448 + buf * 4096 + (lane << 2);
#pragma unroll
        for (int g = 0; g < 8; g++) {
            float4 pa = *(float4*)&pw[g * 4];
            float4 pc = *(float4*)&pw[32 + g * 4];
            float4 v0 = *(float4*)&vsp[(g * 4 + 0) * 128];
            float4 v1 = *(float4*)&vsp[(g * 4 + 1) * 128];
            float4 v2 = *(float4*)&vsp[(g * 4 + 2) * 128];
            float4 v3 = *(float4*)&vsp[(g * 4 + 3) * 128];
            o0.x += pa.x * v0.x; o0.y += pa.x * v0.y;
            o0.z += pa.x * v0.z; o0.w += pa.x * v0.w;
            o1.x += pc.x * v0.x; o1.y += pc.x * v0.y;
            o1.z += pc.x * v0.z; o1.w += pc.x * v0.w;
            o0.x += pa.y * v1.x; o0.y += pa.y * v1.y;
            o0.z += pa.y * v1.z; o0.w += pa.y * v1.w;
            o1.x += pc.y * v1.x; o1.y += pc.y * v1.y;
            o1.z += pc.y * v1.z; o1.w += pc.y * v1.w;
            o0.x += pa.z * v2.x; o0.y += pa.z * v2.y;
            o0.z += pa.z * v2.z; o0.w += pa.z * v2.w;
            o1.x += pc.z * v2.x; o1.y += pc.z * v2.y;
            o1.z += pc.z * v2.z; o1.w += pc.z * v2.w;
            o0.x += pa.w * v3.x; o0.y += pa.w * v3.y;
            o0.z += pa.w * v3.z; o0.w += pa.w * v3.w;
            o1.x += pc.w * v3.x; o1.y += pc.w * v3.y;
            o1.z += pc.w * v3.z; o1.w += pc.w * v3.w;
        }
    }

#pragma unroll
    for (int off = 16; off; off >>= 1) {
        l0 += __shfl_xor_sync(0xffffffffu, l0, off);
        l1 += __shfl_xor_sync(0xffffffffu, l1, off);
    }

    int row0 = (b << 8) + q0 + 2 * w;
    if (lane == 0) {
        g_pl[sp * 2048 + row0]     = l0;
        g_pl[sp * 2048 + row0 + 1] = l1;
    }
    *(float4*)&g_po[(sp * 2048 + row0) * 128 + (lane << 2)]       = o0;
    *(float4*)&g_po[(sp * 2048 + row0 + 1) * 128 + (lane << 2)]   = o1;
}

// ----------------------------------------------------------------------------
// Combine partials: out[row,:] = sum_s o_s / sum_s l_s
// ----------------------------------------------------------------------------
__global__ __launch_bounds__(256) void combine_kernel(float* __restrict__ out)
{
    int idx = blockIdx.x * 256 + threadIdx.x;   // 0 .. 65535
    int row = idx >> 5;
    int c   = (idx & 31) << 2;

    float  l = 0.f;
    float4 a = {0.f, 0.f, 0.f, 0.f};
#pragma unroll
    for (int s = 0; s < S_SPLIT; s++) {
        l += g_pl[s * 2048 + row];
        float4 v = *(const float4*)&g_po[(s * 2048 + row) * 128 + c];
        a.x += v.x; a.y += v.y; a.z += v.z; a.w += v.w;
    }
    float inv = 1.0f / l;
    a.x *= inv; a.y *= inv; a.z *= inv; a.w *= inv;
    *(float4*)&out[row * 128 + c] = a;
}

// ----------------------------------------------------------------------------
// Launch
// ----------------------------------------------------------------------------
extern "C" void kernel_launch(void* const* d_in, const int* in_sizes, int n_in,
                              void* d_out, int out_size)
{
    const float* queries    = (const float*)d_in[0];  // [8,256,256]
    const float* keys       = (const float*)d_in[1];  // [8,1024,256]
    const float* values     = (const float*)d_in[2];  // [8,1024,128]
    const int*   valid_lens = (const int*)  d_in[3];  // [8]
    const float* W_q        = (const float*)d_in[4];  // [256,128]
    const float* W_k        = (const float*)d_in[5];  // [256,128]
    const float* w_v        = (const float*)d_in[6];  // [128]
    float*       out        = (float*)d_out;          // [8,256,128]

    cudaFuncSetAttribute(attn_partial_kernel,
                         cudaFuncAttributeMaxDynamicSharedMemorySize,
                         ATTN_SMEM_BYTES);

    // static: block = chunk (masked chunks exit immediately)
    proj_kernel<<<NCHUNK, 256>>>(queries, keys, W_q, W_k, valid_lens);

    dim3 grid(256 / QT, 8, S_SPLIT);
    attn_partial_kernel<<<grid, 256, ATTN_SMEM_BYTES>>>(values, valid_lens, w_v);

    combine_kernel<<<256, 256>>>(out);
}